// round 6
// baseline (speedup 1.0000x reference)
#include <cuda_runtime.h>
#include <stdint.h>

// ---------------------------------------------------------------------------
// ExtractGraph: maxpool2x2 -> +uniform noise -> diagonal-stencil adjacency
// (transposed) -> bernoulli(0.5) dropout. Output float32.
// RNG = JAX threefry2x32, partitionable scheme:
//   split(key)[i]      = both output words of threefry(key, (0, i))
//   random_bits(32)[t] = o0 ^ o1 of threefry(key, (hi(t), lo(t)))
// Both streams (noise, dropout) share the flat index space t = row*2048+col,
// so kernel A computes BOTH ciphers per element and stashes the dropout
// decision as a bitmask; kernel B is then a light, memory-bound stencil.
// ---------------------------------------------------------------------------

#define PM 2048
#define PN 2048

static __device__ float    g_dnT[(size_t)PM * PN];     // d_noised TRANSPOSED: g_dnT[j][i]
static __device__ unsigned g_keep[(size_t)PM * PN / 32];  // bernoulli keep bits
static __device__ unsigned g_min_u;
static __device__ unsigned g_max_u;

__host__ __device__ __forceinline__ uint32_t rotl32(uint32_t x, int d) {
    return (x << d) | (x >> (32 - d));
}

// Threefry-2x32, 20 rounds, exactly as in jax/_src/prng.py.
__host__ __device__ __forceinline__ void tf2x32(uint32_t k0, uint32_t k1,
                                                uint32_t c0, uint32_t c1,
                                                uint32_t& o0, uint32_t& o1) {
    uint32_t ks2 = k0 ^ k1 ^ 0x1BD11BDAu;
    uint32_t x0 = c0 + k0;
    uint32_t x1 = c1 + k1;
#define TFR(R) { x0 += x1; x1 = rotl32(x1, R); x1 ^= x0; }
    TFR(13) TFR(15) TFR(26) TFR(6)
    x0 += k1;  x1 += ks2 + 1u;
    TFR(17) TFR(29) TFR(16) TFR(24)
    x0 += ks2; x1 += k0 + 2u;
    TFR(13) TFR(15) TFR(26) TFR(6)
    x0 += k0;  x1 += k1 + 3u;
    TFR(17) TFR(29) TFR(16) TFR(24)
    x0 += k1;  x1 += ks2 + 4u;
    TFR(13) TFR(15) TFR(26) TFR(6)
    x0 += ks2; x1 += k0 + 5u;
#undef TFR
    o0 = x0; o1 = x1;
}

__device__ __forceinline__ uint32_t tf_bits32(uint32_t k0, uint32_t k1,
                                              uint32_t c0, uint32_t c1) {
    uint32_t o0, o1;
    tf2x32(k0, k1, c0, c1, o0, o1);
    return o0 ^ o1;
}

// JAX uniform(0,1) float32 from 32 random bits.
__device__ __forceinline__ float u01(uint32_t b) {
    return __uint_as_float((b >> 9) | 0x3f800000u) - 1.0f;
}

// Order-preserving float<->uint mapping for atomic min/max (no NaNs in input).
__device__ __forceinline__ unsigned f2sortable(float f) {
    unsigned u = __float_as_uint(f);
    return (u & 0x80000000u) ? ~u : (u | 0x80000000u);
}
__device__ __forceinline__ float sortable2f(unsigned u) {
    unsigned b = (u & 0x80000000u) ? (u ^ 0x80000000u) : ~u;
    return __uint_as_float(b);
}

// Kernel A: maxpool 2x2 + noise cipher + dropout cipher (same flat index),
// transposed d_noised write via smem tile, keep-bitmask write, min/max
// block reduction into global atomics.
// Block (32,8), each thread 4 pool elements; block tile = 32x32 pool elems.
__global__ void __launch_bounds__(256) pool_noise_kernel(
    const float* __restrict__ dc,
    uint32_t kn0, uint32_t kn1, uint32_t kd0, uint32_t kd1) {
    __shared__ float s[32][33];
    const int tx = threadIdx.x, ty = threadIdx.y;
    const int j0 = blockIdx.x * 32;      // pool col tile
    const int i0 = blockIdx.y * 32;      // pool row tile
    const int j  = j0 + tx;

    unsigned lmin = 0xFFFFFFFFu, lmax = 0u;

#pragma unroll
    for (int k = 0; k < 4; ++k) {
        const int i = i0 + ty + 8 * k;
        const float2* row0 = reinterpret_cast<const float2*>(dc + (size_t)(2 * i) * 4096);
        const float2* row1 = reinterpret_cast<const float2*>(dc + (size_t)(2 * i + 1) * 4096);
        const float2 a = __ldg(&row0[j]);
        const float2 b = __ldg(&row1[j]);
        const float p = fmaxf(fmaxf(a.x, a.y), fmaxf(b.x, b.y));

        const unsigned e = f2sortable(p);
        lmin = min(lmin, e);
        lmax = max(lmax, e);

        const uint32_t t = (uint32_t)(i * PN + j);
        // two independent cipher chains -> good ILP
        const uint32_t bn = tf_bits32(kn0, kn1, 0u, t);
        const uint32_t bd = tf_bits32(kd0, kd1, 0u, t);

        s[tx][ty + 8 * k] = p + u01(bn);

        const bool keep = u01(bd) < 0.5f;
        const unsigned ballot = __ballot_sync(0xffffffffu, keep);
        if (tx == 0) g_keep[(size_t)i * (PN / 32) + (j0 >> 5)] = ballot;
    }
    __syncthreads();

    // transposed, coalesced write: g_dnT[j][i]
#pragma unroll
    for (int k = 0; k < 4; ++k) {
        const int lj = ty + 8 * k;
        g_dnT[(size_t)(j0 + lj) * PM + i0 + tx] = s[lj][tx];
    }

    // block min/max reduction (blockDim.x==32 => ty is the warp id)
    lmin = __reduce_min_sync(0xffffffffu, lmin);
    lmax = __reduce_max_sync(0xffffffffu, lmax);
    __shared__ unsigned rmin[8], rmax[8];
    if (tx == 0) { rmin[ty] = lmin; rmax[ty] = lmax; }
    __syncthreads();
    if (ty == 0 && tx == 0) {
        unsigned m0 = rmin[0], m1 = rmax[0];
#pragma unroll
        for (int w = 1; w < 8; ++w) { m0 = min(m0, rmin[w]); m1 = max(m1, rmax[w]); }
        atomicMin(&g_min_u, m0);
        atomicMax(&g_max_u, m1);
    }
}

// Kernel B: out[r][c] (FLOAT) = keep(r,c) & OR_{dx,dy in +-1} mask(i=c,j=r) &
//                               |dn[c+dy][r+dx] - dn[c][r]| <= thr
// with dn accessed through its transpose g_dnT (coalesced), keep from the
// precomputed L2-resident bitmask. Light, memory-bound.
__global__ void __launch_bounds__(256) graph_kernel(float* __restrict__ out) {
    const int c = blockIdx.x * 32 + threadIdx.x;
    const int r = blockIdx.y * 8 + threadIdx.y;

    const float thr = (sortable2f(g_max_u) - sortable2f(g_min_u)) / 2048.0f;

    const float center = g_dnT[(size_t)r * PM + c];
    bool adj = false;
#pragma unroll
    for (int dx = -1; dx <= 1; dx += 2) {
#pragma unroll
        for (int dy = -1; dy <= 1; dy += 2) {
            // reference mask at (i=c, j=r), all six original conditions:
            const bool m = (c + dx >= 0) && (c + dy < PM) && (r + dx >= 0) &&
                           (r + dy < PN) && (c + dy >= 0) && (r + dx < PN);
            if (m) {
                const float v = g_dnT[(size_t)(r + dx) * PM + (c + dy)];
                adj |= (fabsf(v - center) <= thr);
            }
        }
    }

    const uint32_t idx = (uint32_t)(r * PN + c);
    const unsigned kw = g_keep[idx >> 5];
    const bool keep = (kw >> (c & 31)) & 1u;

    out[idx] = (adj && keep) ? 1.0f : 0.0f;
}

extern "C" void kernel_launch(void* const* d_in, const int* in_sizes, int n_in,
                              void* d_out, int out_size) {
    (void)in_sizes; (void)n_in; (void)out_size;
    const float* dc = (const float*)d_in[0];
    float* out = (float*)d_out;

    // jax.random.key(1) -> (0,1). Partitionable split:
    //   k_noise = words of threefry((0,1), (0,0))
    //   k_drop  = words of threefry((0,1), (0,1))
    uint32_t kn0, kn1, kd0, kd1;
    tf2x32(0u, 1u, 0u, 0u, kn0, kn1);
    tf2x32(0u, 1u, 0u, 1u, kd0, kd1);

    // reset min/max accumulators via graph memset nodes (no init kernel)
    void* pmin = nullptr; void* pmax = nullptr;
    cudaGetSymbolAddress(&pmin, g_min_u);
    cudaGetSymbolAddress(&pmax, g_max_u);
    cudaMemsetAsync(pmin, 0xFF, 4);  // 0xFFFFFFFF
    cudaMemsetAsync(pmax, 0x00, 4);  // 0x00000000

    pool_noise_kernel<<<dim3(64, 64), dim3(32, 8)>>>(dc, kn0, kn1, kd0, kd1);
    graph_kernel<<<dim3(64, 256), dim3(32, 8)>>>(out);
}

// round 7
// speedup vs baseline: 1.2855x; 1.2855x over previous
#include <cuda_runtime.h>
#include <stdint.h>

// ---------------------------------------------------------------------------
// ExtractGraph: maxpool2x2 -> +uniform noise -> diagonal-stencil adjacency
// (transposed) -> bernoulli(0.5) dropout. Output float32.
// RNG = JAX threefry2x32, partitionable scheme:
//   split(key)[i]      = both output words of threefry(key, (0, i))
//   random_bits(32)[t] = o0 ^ o1 of threefry(key, (hi(t), lo(t)))
// Noise cipher lives in the mem-bound pool kernel; dropout cipher lives in
// the stencil kernel (which has ALU headroom after mask simplification).
// ---------------------------------------------------------------------------

#define PM 2048
#define PN 2048

static __device__ float    g_dnT[(size_t)PM * PN];   // d_noised TRANSPOSED: g_dnT[j][i]
static __device__ unsigned g_min_u;
static __device__ unsigned g_max_u;

__host__ __device__ __forceinline__ uint32_t rotl32(uint32_t x, int d) {
    return (x << d) | (x >> (32 - d));
}

// Threefry-2x32, 20 rounds, exactly as in jax/_src/prng.py.
__host__ __device__ __forceinline__ void tf2x32(uint32_t k0, uint32_t k1,
                                                uint32_t c0, uint32_t c1,
                                                uint32_t& o0, uint32_t& o1) {
    uint32_t ks2 = k0 ^ k1 ^ 0x1BD11BDAu;
    uint32_t x0 = c0 + k0;
    uint32_t x1 = c1 + k1;
#define TFR(R) { x0 += x1; x1 = rotl32(x1, R); x1 ^= x0; }
    TFR(13) TFR(15) TFR(26) TFR(6)
    x0 += k1;  x1 += ks2 + 1u;
    TFR(17) TFR(29) TFR(16) TFR(24)
    x0 += ks2; x1 += k0 + 2u;
    TFR(13) TFR(15) TFR(26) TFR(6)
    x0 += k0;  x1 += k1 + 3u;
    TFR(17) TFR(29) TFR(16) TFR(24)
    x0 += k1;  x1 += ks2 + 4u;
    TFR(13) TFR(15) TFR(26) TFR(6)
    x0 += ks2; x1 += k0 + 5u;
#undef TFR
    o0 = x0; o1 = x1;
}

__device__ __forceinline__ uint32_t tf_bits32(uint32_t k0, uint32_t k1,
                                              uint32_t c0, uint32_t c1) {
    uint32_t o0, o1;
    tf2x32(k0, k1, c0, c1, o0, o1);
    return o0 ^ o1;
}

// JAX uniform(0,1) float32 from 32 random bits.
__device__ __forceinline__ float u01(uint32_t b) {
    return __uint_as_float((b >> 9) | 0x3f800000u) - 1.0f;
}

// Order-preserving float<->uint mapping for atomic min/max (no NaNs in input).
__device__ __forceinline__ unsigned f2sortable(float f) {
    unsigned u = __float_as_uint(f);
    return (u & 0x80000000u) ? ~u : (u | 0x80000000u);
}
__device__ __forceinline__ float sortable2f(unsigned u) {
    unsigned b = (u & 0x80000000u) ? (u ^ 0x80000000u) : ~u;
    return __uint_as_float(b);
}

// Kernel A: maxpool 2x2 + threefry noise, write d_noised transposed via smem
// tile; block-reduce min/max of d_pool into global atomics.
__global__ void __launch_bounds__(256) pool_noise_kernel(
    const float* __restrict__ dc, uint32_t kn0, uint32_t kn1) {
    __shared__ float s[32][33];
    const int tx = threadIdx.x, ty = threadIdx.y;
    const int j0 = blockIdx.x * 32;      // pool col tile
    const int i0 = blockIdx.y * 32;      // pool row tile
    const int j  = j0 + tx;

    unsigned lmin = 0xFFFFFFFFu, lmax = 0u;

#pragma unroll
    for (int k = 0; k < 4; ++k) {
        const int i = i0 + ty + 8 * k;
        const float2* row0 = reinterpret_cast<const float2*>(dc + ((uint32_t)(2 * i) << 12));
        const float2* row1 = reinterpret_cast<const float2*>(dc + ((uint32_t)(2 * i + 1) << 12));
        const float2 a = __ldg(&row0[j]);
        const float2 b = __ldg(&row1[j]);
        const float p = fmaxf(fmaxf(a.x, a.y), fmaxf(b.x, b.y));

        const unsigned e = f2sortable(p);
        lmin = min(lmin, e);
        lmax = max(lmax, e);

        const uint32_t bits = tf_bits32(kn0, kn1, 0u, ((uint32_t)i << 11) + j);
        s[tx][ty + 8 * k] = p + u01(bits);
    }
    __syncthreads();

    // transposed, coalesced write: g_dnT[j][i]
#pragma unroll
    for (int k = 0; k < 4; ++k) {
        const int lj = ty + 8 * k;
        g_dnT[((uint32_t)(j0 + lj) << 11) + i0 + tx] = s[lj][tx];
    }

    lmin = __reduce_min_sync(0xffffffffu, lmin);
    lmax = __reduce_max_sync(0xffffffffu, lmax);
    __shared__ unsigned rmin[8], rmax[8];
    if (tx == 0) { rmin[ty] = lmin; rmax[ty] = lmax; }
    __syncthreads();
    if (ty == 0 && tx == 0) {
        unsigned m0 = rmin[0], m1 = rmax[0];
#pragma unroll
        for (int w = 1; w < 8; ++w) { m0 = min(m0, rmin[w]); m1 = max(m1, rmax[w]); }
        atomicMin(&g_min_u, m0);
        atomicMax(&g_max_u, m1);
    }
}

// Kernel B: 4 elements/thread, float4 I/O, 32-bit indexing, simplified mask.
// For output (r,c) (reference i=c, j=r) the six conditions collapse to:
//   (dx=-1,dy=-1): c>=1           && r>=1            nb = dn[r-1][c-1]
//   (dx=-1,dy=+1): c>=1 && c<=2046&& r>=1 && r<=2046 nb = dn[r-1][c+1]
//   (dx=+1,dy=-1): c>=1           && r<=2046         nb = dn[r+1][c-1]
//   (dx=+1,dy=+1): c<=2046        && r<=2046         nb = dn[r+1][c+1]
// keep = top bit of random bits clear (u01(b) < 0.5 exactly).
__global__ void __launch_bounds__(256) graph_kernel(
    float* __restrict__ out, uint32_t kd0, uint32_t kd1) {
    const int c0 = (blockIdx.x * 32 + threadIdx.x) * 4;
    const int r  = blockIdx.y * 8 + threadIdx.y;

    const float thr = (sortable2f(g_max_u) - sortable2f(g_min_u)) * (1.0f / 2048.0f);

    const bool rm = (r >= 1), rp = (r <= PM - 2);
    const uint32_t rowb = (uint32_t)r << 11;
    const float4 ctr = *reinterpret_cast<const float4*>(&g_dnT[rowb + c0]);

    const float* up_row = &g_dnT[(uint32_t)(rm ? r - 1 : r) << 11];
    const float* dn_row = &g_dnT[(uint32_t)(rp ? r + 1 : r) << 11];
    const int cl = (c0 > 0) ? c0 - 1 : 0;
    const int cr = (c0 + 4 < PN) ? c0 + 4 : PN - 1;

    float up[6], dw[6];
    {
        const float4 u4 = *reinterpret_cast<const float4*>(up_row + c0);
        const float4 d4 = *reinterpret_cast<const float4*>(dn_row + c0);
        up[1] = u4.x; up[2] = u4.y; up[3] = u4.z; up[4] = u4.w;
        dw[1] = d4.x; dw[2] = d4.y; dw[3] = d4.z; dw[4] = d4.w;
        up[0] = up_row[cl]; up[5] = up_row[cr];
        dw[0] = dn_row[cl]; dw[5] = dn_row[cr];
    }

    const float cx[4] = {ctr.x, ctr.y, ctr.z, ctr.w};
    float res[4];
#pragma unroll
    for (int e = 0; e < 4; ++e) {
        const int c = c0 + e;
        const bool cm = (c >= 1), cp = (c <= PN - 2);
        const float x = cx[e];
        bool adj = false;
        adj |= (cm && rm)             && (fabsf(up[e]     - x) <= thr);
        adj |= (cm && cp && rm && rp) && (fabsf(up[e + 2] - x) <= thr);
        adj |= (cm && rp)             && (fabsf(dw[e]     - x) <= thr);
        adj |= (cp && rp)             && (fabsf(dw[e + 2] - x) <= thr);

        const uint32_t bd = tf_bits32(kd0, kd1, 0u, rowb + (uint32_t)c);
        res[e] = (adj && !(bd & 0x80000000u)) ? 1.0f : 0.0f;
    }

    *reinterpret_cast<float4*>(&out[rowb + c0]) =
        make_float4(res[0], res[1], res[2], res[3]);
}

extern "C" void kernel_launch(void* const* d_in, const int* in_sizes, int n_in,
                              void* d_out, int out_size) {
    (void)in_sizes; (void)n_in; (void)out_size;
    const float* dc = (const float*)d_in[0];
    float* out = (float*)d_out;

    // jax.random.key(1) -> (0,1). Partitionable split:
    uint32_t kn0, kn1, kd0, kd1;
    tf2x32(0u, 1u, 0u, 0u, kn0, kn1);   // k_noise
    tf2x32(0u, 1u, 0u, 1u, kd0, kd1);   // k_drop

    void* pmin = nullptr; void* pmax = nullptr;
    cudaGetSymbolAddress(&pmin, g_min_u);
    cudaGetSymbolAddress(&pmax, g_max_u);
    cudaMemsetAsync(pmin, 0xFF, 4);
    cudaMemsetAsync(pmax, 0x00, 4);

    pool_noise_kernel<<<dim3(64, 64), dim3(32, 8)>>>(dc, kn0, kn1);
    graph_kernel<<<dim3(16, 256), dim3(32, 8)>>>(out, kd0, kd1);
}